// round 4
// baseline (speedup 1.0000x reference)
#include <cuda_runtime.h>
#include <cuda_bf16.h>

// Soft quantizer forward (levels = linspace(-2,2,25), uniform):
//   x_ste == x_hard == -2 + rint((x+2)*6)/6,  symbols = rint((x+2)*6).
// High-concurrency streamer: 1536 blocks x 256 thr x 4 float4 (exact cover,
// no predicates), loads front-batched (MLP=4), 12 STG.128 per thread.

#define VPT 4

__device__ __forceinline__ float4 quant_h(float4 v, float4* s) {
    const float STEP = 0.16666667f;   // 1/6
    float r0 = rintf(fminf(fmaxf(fmaf(v.x, 6.0f, 12.0f), 0.0f), 24.0f));
    float r1 = rintf(fminf(fmaxf(fmaf(v.y, 6.0f, 12.0f), 0.0f), 24.0f));
    float r2 = rintf(fminf(fmaxf(fmaf(v.z, 6.0f, 12.0f), 0.0f), 24.0f));
    float r3 = rintf(fminf(fmaxf(fmaf(v.w, 6.0f, 12.0f), 0.0f), 24.0f));
    *s = make_float4(r0, r1, r2, r3);
    return make_float4(fmaf(r0, STEP, -2.0f), fmaf(r1, STEP, -2.0f),
                       fmaf(r2, STEP, -2.0f), fmaf(r3, STEP, -2.0f));
}

__global__ void __launch_bounds__(256, 6)
softquant_fast(const float4* __restrict__ x4,
               float4* __restrict__ o0,
               float4* __restrict__ o1,
               float4* __restrict__ o2,
               int nblocks) {
    const int base   = blockIdx.x * (256 * VPT) + threadIdx.x;
    const int stride = 256;

    float4 v[VPT];
    #pragma unroll
    for (int k = 0; k < VPT; k++)
        v[k] = x4[base + k * stride];          // front-batched, MLP=4

    #pragma unroll
    for (int k = 0; k < VPT; k++) {
        float4 s4;
        float4 h4 = quant_h(v[k], &s4);
        int i = base + k * stride;
        o0[i] = h4;                            // x_ste (forward == x_hard)
        if (nblocks >= 2) o1[i] = h4;          // x_hard
        if (nblocks >= 3) o2[i] = s4;          // symbols (as float)
    }
}

__global__ void __launch_bounds__(256)
softquant_generic(const float4* __restrict__ x4,
                  float4* __restrict__ o0,
                  float4* __restrict__ o1,
                  float4* __restrict__ o2,
                  int n4, int nblocks) {
    int i = blockIdx.x * blockDim.x + threadIdx.x;
    if (i >= n4) return;
    float4 s4;
    float4 h4 = quant_h(x4[i], &s4);
    o0[i] = h4;
    if (nblocks >= 2) o1[i] = h4;
    if (nblocks >= 3) o2[i] = s4;
}

extern "C" void kernel_launch(void* const* d_in, const int* in_sizes, int n_in,
                              void* d_out, int out_size) {
    const float* x = (const float*)d_in[0];
    float* out     = (float*)d_out;

    int n  = in_sizes[0];
    int n4 = n / 4;                     // 1572864 for the bench shape

    int nblocks = out_size / n;         // packed output tensors (expect 3)
    if (nblocks < 1) nblocks = 1;
    if (nblocks > 3) nblocks = 3;

    const float4* x4 = (const float4*)x;
    float4* o0 = (float4*)out;
    float4* o1 = (float4*)(out + (size_t)n);
    float4* o2 = (float4*)(out + 2 * (size_t)n);

    const int tile = 256 * VPT;         // 1024 float4 per block
    if ((n % 4 == 0) && (n4 % tile == 0)) {
        softquant_fast<<<n4 / tile, 256>>>(x4, o0, o1, o2, nblocks);
    } else {
        int blocks = (n4 + 255) / 256;
        softquant_generic<<<blocks, 256>>>(x4, o0, o1, o2, n4, nblocks);
    }
}

// round 5
// speedup vs baseline: 1.0019x; 1.0019x over previous
#include <cuda_runtime.h>
#include <cuda_bf16.h>

// Soft quantizer forward (levels = linspace(-2,2,25), uniform):
//   x_ste == x_hard == -2 + rint((x+2)*6)/6,  symbols = rint((x+2)*6).
//
// Traffic is mandatory: 24 MB read + 72 MB write = 96 MB through LTS, which
// sits at the measured full-chip cap (~6300 B/cyc). This kernel is shaped to
// run at that cap: exact-cover grid (no predicates/tail), MLP=2 front-batched
// loads, high occupancy, default cache policy (keep working set L2-resident
// across graph replays).

#define VPT 2   // float4 vectors per thread

__device__ __forceinline__ float4 quant_h(float4 v, float4* s) {
    const float STEP = 0.16666667f;   // 1/6
    float r0 = rintf(fminf(fmaxf(fmaf(v.x, 6.0f, 12.0f), 0.0f), 24.0f));
    float r1 = rintf(fminf(fmaxf(fmaf(v.y, 6.0f, 12.0f), 0.0f), 24.0f));
    float r2 = rintf(fminf(fmaxf(fmaf(v.z, 6.0f, 12.0f), 0.0f), 24.0f));
    float r3 = rintf(fminf(fmaxf(fmaf(v.w, 6.0f, 12.0f), 0.0f), 24.0f));
    *s = make_float4(r0, r1, r2, r3);
    return make_float4(fmaf(r0, STEP, -2.0f), fmaf(r1, STEP, -2.0f),
                       fmaf(r2, STEP, -2.0f), fmaf(r3, STEP, -2.0f));
}

__global__ void __launch_bounds__(256, 8)
softquant_fast(const float4* __restrict__ x4,
               float4* __restrict__ o0,
               float4* __restrict__ o1,
               float4* __restrict__ o2,
               int nblocks) {
    // Exact cover: each block owns a contiguous tile of 256*VPT float4,
    // each thread handles VPT strided float4 within the tile (keeps every
    // LDG/STG.128 instruction inside 4 cache lines).
    const int base = blockIdx.x * (256 * VPT) + threadIdx.x;

    float4 v[VPT];
    #pragma unroll
    for (int k = 0; k < VPT; k++)
        v[k] = x4[base + k * 256];             // front-batched, MLP=2

    #pragma unroll
    for (int k = 0; k < VPT; k++) {
        float4 s4;
        float4 h4 = quant_h(v[k], &s4);
        int i = base + k * 256;
        o0[i] = h4;                            // x_ste (forward == x_hard)
        if (nblocks >= 2) o1[i] = h4;          // x_hard
        if (nblocks >= 3) o2[i] = s4;          // symbols (as float)
    }
}

__global__ void __launch_bounds__(256)
softquant_generic(const float4* __restrict__ x4,
                  float4* __restrict__ o0,
                  float4* __restrict__ o1,
                  float4* __restrict__ o2,
                  int n4, int nblocks) {
    int i = blockIdx.x * blockDim.x + threadIdx.x;
    if (i >= n4) return;
    float4 s4;
    float4 h4 = quant_h(x4[i], &s4);
    o0[i] = h4;
    if (nblocks >= 2) o1[i] = h4;
    if (nblocks >= 3) o2[i] = s4;
}

extern "C" void kernel_launch(void* const* d_in, const int* in_sizes, int n_in,
                              void* d_out, int out_size) {
    const float* x = (const float*)d_in[0];
    float* out     = (float*)d_out;

    int n  = in_sizes[0];
    int n4 = n / 4;                     // 1,572,864 for the bench shape

    int nblocks = out_size / n;         // packed output tensors (expect 3)
    if (nblocks < 1) nblocks = 1;
    if (nblocks > 3) nblocks = 3;

    const float4* x4 = (const float4*)x;
    float4* o0 = (float4*)out;
    float4* o1 = (float4*)(out + (size_t)n);
    float4* o2 = (float4*)(out + 2 * (size_t)n);

    const int tile = 256 * VPT;         // 512 float4 per block
    if ((n % 4 == 0) && (n4 % tile == 0)) {
        softquant_fast<<<n4 / tile, 256>>>(x4, o0, o1, o2, nblocks);  // 3072 blocks
    } else {
        int blocks = (n4 + 255) / 256;
        softquant_generic<<<blocks, 256>>>(x4, o0, o1, o2, n4, nblocks);
    }
}